// round 4
// baseline (speedup 1.0000x reference)
#include <cuda_runtime.h>

// LearnableShiftViews: out[v,b,c,h,w] = separable bilinear resample of x[b,c]
// at pix = (idx + d)*size/(size-1) - 0.5 per axis, zero padding.
//
// R4: transpose the work mapping to amortize coefficient math (R3 was
// issue-bound on it). Warp = 32-wide x-strip; each thread iterates the 8
// y-rows of the tile, so the x-coefficients (ix0/fx/p0) are computed once
// per (view, strip) and reused 8x. y-coefficients {wy0, wy1, row byte
// offsets} are per-(v, ty) and warp-uniform: built once per block into a
// 640 B smem table, fetched in-loop with a single broadcast LDS.128.
// Zero-padded smem rows (2 cols each side) keep the x-blend mask-free.
// Hot iteration: 1 bcast LDS + 2 IADD + 4 LDS.32 + 6 FP + 1 STG.

namespace {

constexpr int H = 224;
constexpr int W = 224;
constexpr int B = 64;
constexpr int C = 3;
constexpr int BCN = B * C;   // 192
constexpr int V = 5;
constexpr int TILE_Y = 8;
constexpr int ROWS_CAP = 16;
constexpr int NTHREADS = 224;          // 7 warps = 7 x-strips (W = 7*32)
constexpr int RS = 228;                // [0,1]=pad0, [2..225]=data, [226,227]=pad0

__global__ __launch_bounds__(NTHREADS)
void shift_views_kernel(const float* __restrict__ x,
                        const float* __restrict__ offs,
                        float* __restrict__ out) {
    __shared__ float  srows[ROWS_CAP * RS];
    __shared__ float4 ycoef[V][TILE_Y];   // {wy0, wy1, byteoff(row0), byteoff(row1)}

    const int yb  = blockIdx.x * TILE_Y;
    const int bc  = blockIdx.y;
    const int tid = threadIdx.x;
    const float sy = (float)H / (float)(H - 1);
    const float sx = (float)W / (float)(W - 1);

    // ---- Row range needed across all views (endpoints suffice; monotone).
    int rmin = H - 1, rmax = 0;
#pragma unroll
    for (int v = 0; v < V; ++v) {
        float dy = __ldg(&offs[2 * v]);
        int lo = (int)floorf(((float)yb + dy) * sy - 0.5f);
        int hi = (int)floorf(((float)(yb + TILE_Y - 1) + dy) * sy - 0.5f) + 1;
        lo = max(lo, 0);
        hi = min(hi, H - 1);
        rmin = min(rmin, lo);
        rmax = max(rmax, hi);
    }
    if (rmin > rmax) { rmin = 0; rmax = 0; }
    rmax = min(rmax, rmin + ROWS_CAP - 1);
    const int nrows = rmax - rmin + 1;

    // ---- Zero the 4 pad columns of every staged row.
    if (tid < ROWS_CAP * 4) {
        int r = tid >> 2, c = tid & 3;
        srows[r * RS + (c < 2 ? c : 224 + c)] = 0.0f;   // cols 0,1,226,227
    }

    // ---- Build y-coefficient table: one thread per (v, ty).
    if (tid < V * TILE_Y) {
        int v  = tid >> 3;
        int t  = tid & 7;
        float dy   = offs[2 * v];
        float ypix = ((float)(yb + t) + dy) * sy - 0.5f;
        float py   = floorf(ypix);
        float fy   = ypix - py;
        int   iy0  = (int)py;
        float wy0  = ((unsigned)iy0       < (unsigned)H) ? (1.0f - fy) : 0.0f;
        float wy1  = ((unsigned)(iy0 + 1) < (unsigned)H) ? fy          : 0.0f;
        int r0 = min(max(iy0,     rmin), rmax) - rmin;
        int r1 = min(max(iy0 + 1, rmin), rmax) - rmin;
        ycoef[v][t] = make_float4(wy0, wy1,
                                  __int_as_float(r0 * RS * 4),
                                  __int_as_float(r1 * RS * 4));
    }

    // ---- Stage input rows into padded smem (float2, coalesced).
    {
        const float2* src = reinterpret_cast<const float2*>(
            x + (size_t)bc * (H * W) + (size_t)rmin * W);
        const int n2 = nrows * (W / 2);
        for (int i = tid; i < n2; i += NTHREADS) {
            int r = i / (W / 2);
            int c = i - r * (W / 2);
            reinterpret_cast<float2*>(&srows[r * RS + 2])[c] = src[r * (W / 2) + c];
        }
    }
    __syncthreads();

    // ---- Compute: warp w owns x-strip [32w, 32w+32); thread iterates 8 rows.
    const int lane = tid & 31;
    const int xx   = (tid >> 5) * 32 + lane;
    const char* sb = (const char*)srows;

#pragma unroll 1
    for (int v = 0; v < V; ++v) {
        const float dx = __ldg(&offs[2 * v + 1]);

        // x coefficients: once per (view, strip), reused for all 8 rows.
        float xpix = fmaf((float)xx, sx, dx * sx - 0.5f);
        int   ix0  = __float2int_rd(xpix);
        float fx   = xpix - (float)ix0;
        int   p0b  = min(max(ix0 + 2, 0), RS - 2) * 4;   // byte offset; pads absorb edges

        float* __restrict__ obase =
            out + (((size_t)(v * BCN + bc)) * H + yb) * W + xx;

#pragma unroll
        for (int ty = 0; ty < TILE_Y; ++ty) {
            float4 yc = ycoef[v][ty];                    // broadcast: 1 wavefront
            const float* pr0 = (const float*)(sb + (__float_as_int(yc.z) + p0b));
            const float* pr1 = (const float*)(sb + (__float_as_int(yc.w) + p0b));
            float a0 = pr0[0], a1 = pr0[1];
            float b0 = pr1[0], b1 = pr1[1];
            float t0 = fmaf(fx, a1 - a0, a0);            // mask-free lerp (pads=0)
            float t1 = fmaf(fx, b1 - b0, b0);
            obase[ty * W] = fmaf(t1, yc.y, t0 * yc.x);   // coalesced 128B/warp
        }
    }
}

}  // namespace

extern "C" void kernel_launch(void* const* d_in, const int* in_sizes, int n_in,
                              void* d_out, int out_size) {
    const float* x    = (const float*)d_in[0];
    const float* offs = (const float*)d_in[1];
    if (n_in >= 2 && in_sizes[0] == 2 * V) {   // tolerate swapped metadata order
        const float* t = x; x = offs; offs = t;
    }
    dim3 grid(H / TILE_Y, BCN);
    shift_views_kernel<<<grid, NTHREADS>>>(x, offs, (float*)d_out);
}